// round 5
// baseline (speedup 1.0000x reference)
#include <cuda_runtime.h>

// NCDE decoder: B=4096, 255 RK4 steps, C=16, H=128, O=4.
// One 128-thread block per TWO batch elements (weights shared in registers,
// two independent dependency chains interleaved per thread to hide the
// per-stage reduction latency). Quad-reciprocal tanh; fma.rn.f32x2 packing.

#define Hh 128
#define Cc 16
#define NSTEP 255
#define L2E2 2.8853900817779268f   // 2*log2(e), folded into W2/b2

typedef unsigned long long ull;

__device__ __forceinline__ ull pack2(float lo, float hi) {
    ull r; asm("mov.b64 %0, {%1, %2};" : "=l"(r) : "f"(lo), "f"(hi)); return r;
}
__device__ __forceinline__ void unpack2(ull v, float& lo, float& hi) {
    asm("mov.b64 {%0, %1}, %2;" : "=f"(lo), "=f"(hi) : "l"(v));
}
__device__ __forceinline__ ull fma2(ull a, ull b, ull c) {
    ull d; asm("fma.rn.f32x2 %0, %1, %2, %3;" : "=l"(d) : "l"(a), "l"(b), "l"(c)); return d;
}
__device__ __forceinline__ float ex2f(float x) {
    float e; asm("ex2.approx.f32 %0, %1;" : "=f"(e) : "f"(x)); return e;
}
__device__ __forceinline__ float rcpf(float x) {
    float r; asm("rcp.approx.f32 %0, %1;" : "=f"(r) : "f"(x)); return r;
}

__device__ __forceinline__ void redsum4(float& a, float& b, float& c, float& d) {
#pragma unroll
    for (int off = 16; off; off >>= 1) {
        a += __shfl_xor_sync(0xffffffffu, a, off);
        b += __shfl_xor_sync(0xffffffffu, b, off);
        c += __shfl_xor_sync(0xffffffffu, c, off);
        d += __shfl_xor_sync(0xffffffffu, d, off);
    }
}
__device__ __forceinline__ void redsum8(float* v) {
#pragma unroll
    for (int off = 16; off; off >>= 1) {
#pragma unroll
        for (int i = 0; i < 8; i++)
            v[i] += __shfl_xor_sync(0xffffffffu, v[i], off);
    }
}

__global__ __launch_bounds__(128) void ncde_kernel(
    const float* __restrict__ coeffs,   // (B, 255, 64)
    const float* __restrict__ W_init,   // (16, 128)
    const float* __restrict__ b_init,   // (128)
    const float* __restrict__ W1,       // (128, 2)
    const float* __restrict__ b1,       // (2)
    const float* __restrict__ W2,       // (2, 2048)
    const float* __restrict__ b2,       // (2048)
    const float* __restrict__ W_out,    // (128, 4)
    const float* __restrict__ b_out,    // (4)
    float* __restrict__ out)            // (B, 256, 4)
{
    const int h    = threadIdx.x;
    const int lane = h & 31;
    const int warp = h >> 5;

    __shared__ __align__(16) float sxd2[2][3][Cc];  // per-batch -2*xdot tables
    __shared__ float ssum[2][3];
    __shared__ float sred[2][16];                   // [phase][warp*4 + j]
    __shared__ float sredo[2][16];
    __shared__ float sa0[2][Cc];

    // ---- shared-weight register slices (arg scale 2*log2e pre-folded) ----
    ull wa[8], wbp[8], b2p[8];
#pragma unroll
    for (int p = 0; p < 8; p++) {
        wa[p]  = pack2(W2[h * Cc + 2 * p] * L2E2,           W2[h * Cc + 2 * p + 1] * L2E2);
        wbp[p] = pack2(W2[Hh * Cc + h * Cc + 2 * p] * L2E2, W2[Hh * Cc + h * Cc + 2 * p + 1] * L2E2);
        b2p[p] = pack2(b2[h * Cc + 2 * p] * L2E2,           b2[h * Cc + 2 * p + 1] * L2E2);
    }
    const float w1a = W1[h * 2 + 0], w1b = W1[h * 2 + 1];
    const float wo0 = W_out[h * 4 + 0], wo1 = W_out[h * 4 + 1];
    const float wo2 = W_out[h * 4 + 2], wo3 = W_out[h * 4 + 3];
    const float b10 = b1[0], b11 = b1[1];
    // threads h<4 write batch A rows (index lane), h=4..7 write batch B rows
    // (index lane-4): both need b_out[lane & 3].
    const float bout = (lane < 8) ? b_out[lane & 3] : 0.0f;

    const float* crowA = coeffs + (size_t)(blockIdx.x * 2 + 0) * (NSTEP * 64);
    const float* crowB = coeffs + (size_t)(blockIdx.x * 2 + 1) * (NSTEP * 64);
    float* outA = out + (size_t)(blockIdx.x * 2 + 0) * 1024;
    float* outB = out + (size_t)(blockIdx.x * 2 + 1) * 1024;

    float pbA = 0.f, pcA = 0.f, pdA = 0.f, pbB = 0.f, pcB = 0.f, pdB = 0.f;
    if (h < Cc) {
        sa0[0][h] = crowA[h]; sa0[1][h] = crowB[h];
        pbA = crowA[16 + h]; pcA = crowA[32 + h]; pdA = crowA[48 + h];
        pbB = crowB[16 + h]; pcB = crowB[32 + h]; pdB = crowB[48 + h];
    }

    // SW1 = column sums of W1
    {
        float r0 = w1a, r1 = w1b, r2 = 0.f, r3 = 0.f;
        redsum4(r0, r1, r2, r3);
        if (lane == 0) { sred[0][warp * 4] = r0; sred[0][warp * 4 + 1] = r1; }
    }
    __syncthreads();
    const float SW1a = sred[0][0] + sred[0][4] + sred[0][8]  + sred[0][12];
    const float SW1b = sred[0][1] + sred[0][5] + sred[0][9]  + sred[0][13];

    // z0 = X0 @ W_init + b_init for both batches
    float zA = b_init[h], zB = zA;
#pragma unroll
    for (int c = 0; c < Cc; c++) {
        const float wi = W_init[c * Hh + h];
        zA = fmaf(sa0[0][c], wi, zA);
        zB = fmaf(sa0[1][c], wi, zB);
    }

    // uz for both batches; output t=0 for both
    float uzA0, uzA1, uzB0, uzB1;
    {
        float r0 = zA * w1a, r1 = zA * w1b, r2 = zB * w1a, r3 = zB * w1b;
        redsum4(r0, r1, r2, r3);
        if (lane == 0) {
            sred[1][warp * 4 + 0] = r0; sred[1][warp * 4 + 1] = r1;
            sred[1][warp * 4 + 2] = r2; sred[1][warp * 4 + 3] = r3;
        }
        float p[8] = { zA * wo0, zA * wo1, zA * wo2, zA * wo3,
                       zB * wo0, zB * wo1, zB * wo2, zB * wo3 };
        redsum8(p);
        if (lane == 0) {
#pragma unroll
            for (int i = 0; i < 4; i++) {
                sredo[0][warp * 4 + i] = p[i];
                sredo[1][warp * 4 + i] = p[4 + i];
            }
        }
        __syncthreads();
        uzA0 = sred[1][0] + sred[1][4] + sred[1][8]  + sred[1][12];
        uzA1 = sred[1][1] + sred[1][5] + sred[1][9]  + sred[1][13];
        uzB0 = sred[1][2] + sred[1][6] + sred[1][10] + sred[1][14];
        uzB1 = sred[1][3] + sred[1][7] + sred[1][11] + sred[1][15];
        if (h < 4)
            outA[h] = sredo[0][h] + sredo[0][4 + h] + sredo[0][8 + h] + sredo[0][12 + h] + bout;
        else if (h < 8)
            outB[lane - 4] = sredo[1][lane - 4] + sredo[1][lane] + sredo[1][4 + lane] + sredo[1][8 + lane] + bout;
    }

    int ph = 0;
    for (int t = 0; t < NSTEP; t++) {
        if (h < Cc) {
            sxd2[0][0][h] = -2.f * pbA;
            sxd2[0][1][h] = -2.f * fmaf(0.25f, pdA, fmaf(0.5f, pcA, pbA));
            sxd2[0][2][h] = -2.f * (pbA + pcA + pdA);
            sxd2[1][0][h] = -2.f * pbB;
            sxd2[1][1][h] = -2.f * fmaf(0.25f, pdB, fmaf(0.5f, pcB, pbB));
            sxd2[1][2][h] = -2.f * (pbB + pcB + pdB);
        }
        if (warp == 0) {   // lanes >= 16 hold zeros
            float v[6] = { pbA, pcA, pdA, pbB, pcB, pdB };
#pragma unroll
            for (int off = 1; off < 16; off <<= 1)
#pragma unroll
                for (int i = 0; i < 6; i++)
                    v[i] += __shfl_xor_sync(0xffffffffu, v[i], off);
            if (lane == 0) {
                ssum[0][0] = v[0];
                ssum[0][1] = fmaf(0.25f, v[2], fmaf(0.5f, v[1], v[0]));
                ssum[0][2] = v[0] + v[1] + v[2];
                ssum[1][0] = v[3];
                ssum[1][1] = fmaf(0.25f, v[5], fmaf(0.5f, v[4], v[3]));
                ssum[1][2] = v[3] + v[4] + v[5];
            }
        }
        __syncthreads();
        if (h < Cc && (t + 1) < NSTEP) {
            const float* rA = crowA + (size_t)(t + 1) * 64;
            const float* rB = crowB + (size_t)(t + 1) * 64;
            pbA = rA[16 + h]; pcA = rA[32 + h]; pdA = rA[48 + h];
            pbB = rB[16 + h]; pcB = rB[32 + h]; pdB = rB[48 + h];
        }
        const float SA0 = ssum[0][0], SAh = ssum[0][1], SA1 = ssum[0][2];
        const float SB0 = ssum[1][0], SBh = ssum[1][1], SB1 = ssum[1][2];

        float ukA0 = 0.f, ukA1 = 0.f, sA0 = 0.f, sA1 = 0.f, ksumA = 0.f;
        float ukB0 = 0.f, ukB1 = 0.f, sB0 = 0.f, sB1 = 0.f, ksumB = 0.f;

#pragma unroll
        for (int st = 0; st < 4; st++) {
            const float alpha = (st == 0) ? 0.f : (st == 3) ? 1.f : 0.5f;
            const int   xi    = (st == 0) ? 0   : (st == 3) ? 2   : 1;
            const float wgt   = (st == 0 || st == 3) ? 1.f : 2.f;
            const float SstA  = (st == 0) ? SA0 : (st == 3) ? SA1 : SAh;
            const float SstB  = (st == 0) ? SB0 : (st == 3) ? SB1 : SBh;

            const float hA0 = fmaxf(fmaf(alpha, ukA0, uzA0) + b10, 0.f);
            const float hA1 = fmaxf(fmaf(alpha, ukA1, uzA1) + b11, 0.f);
            const float hB0 = fmaxf(fmaf(alpha, ukB0, uzB0) + b10, 0.f);
            const float hB1 = fmaxf(fmaf(alpha, ukB1, uzB1) + b11, 0.f);
            const ull HA0 = pack2(hA0, hA0), HA1 = pack2(hA1, hA1);
            const ull HB0 = pack2(hB0, hB0), HB1 = pack2(hB1, hB1);

            float qA = 0.f, qB = 0.f;
#pragma unroll
            for (int qi = 0; qi < 4; qi++) {
                const ull yA0 = fma2(HA0, wa[2 * qi],     fma2(HA1, wbp[2 * qi],     b2p[2 * qi]));
                const ull yA1 = fma2(HA0, wa[2 * qi + 1], fma2(HA1, wbp[2 * qi + 1], b2p[2 * qi + 1]));
                const ull yB0 = fma2(HB0, wa[2 * qi],     fma2(HB1, wbp[2 * qi],     b2p[2 * qi]));
                const ull yB1 = fma2(HB0, wa[2 * qi + 1], fma2(HB1, wbp[2 * qi + 1], b2p[2 * qi + 1]));
                float a0, a1, a2, a3, e0, e1, e2, e3;
                unpack2(yA0, a0, a1); unpack2(yA1, a2, a3);
                unpack2(yB0, e0, e1); unpack2(yB1, e2, e3);
                const float tA0 = ex2f(fminf(a0, 30.f)) + 1.f;
                const float tA1 = ex2f(fminf(a1, 30.f)) + 1.f;
                const float tA2 = ex2f(fminf(a2, 30.f)) + 1.f;
                const float tA3 = ex2f(fminf(a3, 30.f)) + 1.f;
                const float tB0 = ex2f(fminf(e0, 30.f)) + 1.f;
                const float tB1 = ex2f(fminf(e1, 30.f)) + 1.f;
                const float tB2 = ex2f(fminf(e2, 30.f)) + 1.f;
                const float tB3 = ex2f(fminf(e3, 30.f)) + 1.f;
                const float4 xA = *(const float4*)&sxd2[0][xi][4 * qi];
                const float4 xB = *(const float4*)&sxd2[1][xi][4 * qi];
                const float PA0 = tA0 * tA1, PA1 = tA2 * tA3;
                const float NA0 = fmaf(xA.y, tA0, xA.x * tA1);
                const float NA1 = fmaf(xA.w, tA2, xA.z * tA3);
                const float PB0 = tB0 * tB1, PB1 = tB2 * tB3;
                const float NB0 = fmaf(xB.y, tB0, xB.x * tB1);
                const float NB1 = fmaf(xB.w, tB2, xB.z * tB3);
                const float RA = rcpf(PA0 * PA1);
                const float RB = rcpf(PB0 * PB1);
                qA = fmaf(RA, fmaf(NA1, PA0, NA0 * PA1), qA);
                qB = fmaf(RB, fmaf(NB1, PB0, NB0 * PB1), qB);
            }

            float r0 = qA * w1a, r1 = qA * w1b, r2 = qB * w1a, r3 = qB * w1b;
            redsum4(r0, r1, r2, r3);
            if (lane == 0) {
                sred[ph][warp * 4 + 0] = r0; sred[ph][warp * 4 + 1] = r1;
                sred[ph][warp * 4 + 2] = r2; sred[ph][warp * 4 + 3] = r3;
            }
            __syncthreads();
            const float QA0 = sred[ph][0] + sred[ph][4] + sred[ph][8]  + sred[ph][12];
            const float QA1 = sred[ph][1] + sred[ph][5] + sred[ph][9]  + sred[ph][13];
            const float QB0 = sred[ph][2] + sred[ph][6] + sred[ph][10] + sred[ph][14];
            const float QB1 = sred[ph][3] + sred[ph][7] + sred[ph][11] + sred[ph][15];
            ukA0 = fmaf(SstA, SW1a, QA0);  ukA1 = fmaf(SstA, SW1b, QA1);
            ukB0 = fmaf(SstB, SW1a, QB0);  ukB1 = fmaf(SstB, SW1b, QB1);
            sA0 = fmaf(wgt, ukA0, sA0);    sA1 = fmaf(wgt, ukA1, sA1);
            sB0 = fmaf(wgt, ukB0, sB0);    sB1 = fmaf(wgt, ukB1, sB1);
            ksumA = fmaf(wgt, SstA + qA, ksumA);
            ksumB = fmaf(wgt, SstB + qB, ksumB);
            ph ^= 1;
        }

        zA   = fmaf(ksumA, 1.f / 6.f, zA);
        uzA0 = fmaf(sA0,   1.f / 6.f, uzA0);
        uzA1 = fmaf(sA1,   1.f / 6.f, uzA1);
        zB   = fmaf(ksumB, 1.f / 6.f, zB);
        uzB0 = fmaf(sB0,   1.f / 6.f, uzB0);
        uzB1 = fmaf(sB1,   1.f / 6.f, uzB1);

        // output row t+1, both batches
        float p[8] = { zA * wo0, zA * wo1, zA * wo2, zA * wo3,
                       zB * wo0, zB * wo1, zB * wo2, zB * wo3 };
        redsum8(p);
        if (lane == 0) {
#pragma unroll
            for (int i = 0; i < 4; i++) {
                sredo[0][warp * 4 + i] = p[i];
                sredo[1][warp * 4 + i] = p[4 + i];
            }
        }
        __syncthreads();
        if (h < 4)
            outA[(size_t)(t + 1) * 4 + h] =
                sredo[0][h] + sredo[0][4 + h] + sredo[0][8 + h] + sredo[0][12 + h] + bout;
        else if (h < 8)
            outB[(size_t)(t + 1) * 4 + (lane - 4)] =
                sredo[1][lane - 4] + sredo[1][lane] + sredo[1][4 + lane] + sredo[1][8 + lane] + bout;
    }
}

extern "C" void kernel_launch(void* const* d_in, const int* in_sizes, int n_in,
                              void* d_out, int out_size) {
    const float* coeffs = (const float*)d_in[0];
    const float* W_init = (const float*)d_in[1];
    const float* b_init = (const float*)d_in[2];
    const float* W1     = (const float*)d_in[3];
    const float* b1     = (const float*)d_in[4];
    const float* W2     = (const float*)d_in[5];
    const float* b2     = (const float*)d_in[6];
    const float* W_out  = (const float*)d_in[7];
    const float* b_out  = (const float*)d_in[8];
    float* out = (float*)d_out;

    ncde_kernel<<<2048, 128>>>(coeffs, W_init, b_init, W1, b1, W2, b2,
                               W_out, b_out, out);
}

// round 8
// speedup vs baseline: 1.3780x; 1.3780x over previous
#include <cuda_runtime.h>

// NCDE decoder: B=4096, 255 RK4 steps, C=16, H=128, O=4.
// Kernel 1: one 128-thread block per batch element (thread = h). RK4 scan with
//   quad-reciprocal tanh (1 rcp / 4 tanh) and fma.rn.f32x2 packed arguments.
//   z trajectory is streamed to a __device__ scratch (no in-loop output proj).
// Kernel 2: memory-bound projection out = z_all @ W_out + b_out.

#define Hh 128
#define Cc 16
#define NSTEP 255
#define L2E2 2.8853900817779268f   // 2*log2(e), folded into W2/b2

typedef unsigned long long ull;

__device__ float zscr[4096 * 256 * 128];   // 512 MB z trajectory scratch

__device__ __forceinline__ ull pack2(float lo, float hi) {
    ull r; asm("mov.b64 %0, {%1, %2};" : "=l"(r) : "f"(lo), "f"(hi)); return r;
}
__device__ __forceinline__ void unpack2(ull v, float& lo, float& hi) {
    asm("mov.b64 {%0, %1}, %2;" : "=f"(lo), "=f"(hi) : "l"(v));
}
__device__ __forceinline__ ull fma2(ull a, ull b, ull c) {
    ull d; asm("fma.rn.f32x2 %0, %1, %2, %3;" : "=l"(d) : "l"(a), "l"(b), "l"(c)); return d;
}
__device__ __forceinline__ float ex2f(float x) {
    float e; asm("ex2.approx.f32 %0, %1;" : "=f"(e) : "f"(x)); return e;
}
__device__ __forceinline__ float rcpf(float x) {
    float r; asm("rcp.approx.f32 %0, %1;" : "=f"(r) : "f"(x)); return r;
}

__device__ __forceinline__ void redsum2(float& a, float& b) {
#pragma unroll
    for (int off = 16; off; off >>= 1) {
        a += __shfl_xor_sync(0xffffffffu, a, off);
        b += __shfl_xor_sync(0xffffffffu, b, off);
    }
}
__device__ __forceinline__ void redsum4(float& a, float& b, float& c, float& d) {
#pragma unroll
    for (int off = 16; off; off >>= 1) {
        a += __shfl_xor_sync(0xffffffffu, a, off);
        b += __shfl_xor_sync(0xffffffffu, b, off);
        c += __shfl_xor_sync(0xffffffffu, c, off);
        d += __shfl_xor_sync(0xffffffffu, d, off);
    }
}

__global__ __launch_bounds__(128, 6) void ncde_kernel(
    const float* __restrict__ coeffs,   // (B, 255, 64)
    const float* __restrict__ W_init,   // (16, 128)
    const float* __restrict__ b_init,   // (128)
    const float* __restrict__ W1,       // (128, 2)
    const float* __restrict__ b1,       // (2)
    const float* __restrict__ W2,       // (2, 2048)
    const float* __restrict__ b2)       // (2048)
{
    const int b    = blockIdx.x;
    const int h    = threadIdx.x;
    const int lane = h & 31;
    const int warp = h >> 5;

    __shared__ __align__(16) float sxd2[3][Cc];   // -2*xdot per stage-class
    __shared__ float ssum[3];                     // sum_c xdot_c per stage-class
    __shared__ __align__(16) float sred[2][8];    // double-buffered uk reduction
    __shared__ float sa0[Cc];

    // ---- per-thread packed weight slices (arg scale 2*log2e pre-folded) ----
    ull wa[8], wbp[8], b2p[8];
#pragma unroll
    for (int p = 0; p < 8; p++) {
        wa[p]  = pack2(W2[h * Cc + 2 * p] * L2E2,           W2[h * Cc + 2 * p + 1] * L2E2);
        wbp[p] = pack2(W2[Hh * Cc + h * Cc + 2 * p] * L2E2, W2[Hh * Cc + h * Cc + 2 * p + 1] * L2E2);
        b2p[p] = pack2(b2[h * Cc + 2 * p] * L2E2,           b2[h * Cc + 2 * p + 1] * L2E2);
    }
    const float w1a = W1[h * 2 + 0], w1b = W1[h * 2 + 1];
    const float b10 = b1[0], b11 = b1[1];

    const float* crow = coeffs + (size_t)b * (NSTEP * 64);
    float* zrow = zscr + (size_t)b * (256 * Hh) + h;

    float pb = 0.f, pc = 0.f, pd = 0.f;
    if (h < Cc) { sa0[h] = crow[h]; pb = crow[16 + h]; pc = crow[32 + h]; pd = crow[48 + h]; }

    // SW1 = column sums of W1 (for k = S + q decomposition)
    {
        float r0 = w1a, r1 = w1b;
        redsum2(r0, r1);
        if (lane == 0) { sred[0][warp * 2] = r0; sred[0][warp * 2 + 1] = r1; }
    }
    __syncthreads();
    float SW1a, SW1b;
    {
        const float4 fa = *(const float4*)&sred[0][0];
        const float4 fb = *(const float4*)&sred[0][4];
        SW1a = fa.x + fa.z + fb.x + fb.z;
        SW1b = fa.y + fa.w + fb.y + fb.w;
    }

    // z0 = X0 @ W_init + b_init
    float z = b_init[h];
#pragma unroll
    for (int c = 0; c < Cc; c++) z = fmaf(sa0[c], W_init[c * Hh + h], z);
    zrow[0] = z;

    // uz = z @ W1
    float uz0, uz1;
    {
        float r0 = z * w1a, r1 = z * w1b;
        redsum2(r0, r1);
        if (lane == 0) { sred[1][warp * 2] = r0; sred[1][warp * 2 + 1] = r1; }
        __syncthreads();
        const float4 fa = *(const float4*)&sred[1][0];
        const float4 fb = *(const float4*)&sred[1][4];
        uz0 = fa.x + fa.z + fb.x + fb.z;
        uz1 = fa.y + fa.w + fb.y + fb.w;
    }

    int ph = 0;
    for (int t = 0; t < NSTEP; t++) {
        if (h < Cc) {
            sxd2[0][h] = -2.f * pb;
            sxd2[1][h] = -2.f * fmaf(0.25f, pd, fmaf(0.5f, pc, pb));
            sxd2[2][h] = -2.f * (pb + pc + pd);
        }
        if (warp == 0) {   // lanes >= 16 hold zeros
            float SB = pb, SC = pc, SD = pd;
#pragma unroll
            for (int off = 1; off < 16; off <<= 1) {
                SB += __shfl_xor_sync(0xffffffffu, SB, off);
                SC += __shfl_xor_sync(0xffffffffu, SC, off);
                SD += __shfl_xor_sync(0xffffffffu, SD, off);
            }
            if (lane == 0) {
                ssum[0] = SB;
                ssum[1] = fmaf(0.25f, SD, fmaf(0.5f, SC, SB));
                ssum[2] = SB + SC + SD;
            }
        }
        __syncthreads();
        if (h < Cc && (t + 1) < NSTEP) {       // prefetch next step's coeff row
            const float* r2 = crow + (size_t)(t + 1) * 64;
            pb = r2[16 + h]; pc = r2[32 + h]; pd = r2[48 + h];
        }
        const float S0 = ssum[0], Sh_ = ssum[1], S1 = ssum[2];

        float uk0 = 0.f, uk1 = 0.f, s0 = 0.f, s1 = 0.f, ksum = 0.f;

#pragma unroll
        for (int st = 0; st < 4; st++) {
            const float alpha = (st == 0) ? 0.f : (st == 3) ? 1.f : 0.5f;
            const int   xi    = (st == 0) ? 0   : (st == 3) ? 2   : 1;
            const float wgt   = (st == 0 || st == 3) ? 1.f : 2.f;
            const float Sst   = (st == 0) ? S0 : (st == 3) ? S1 : Sh_;

            const float h0 = fmaxf(fmaf(alpha, uk0, uz0) + b10, 0.f);
            const float h1 = fmaxf(fmaf(alpha, uk1, uz1) + b11, 0.f);
            const ull H0 = pack2(h0, h0), H1 = pack2(h1, h1);

            float qa = 0.f, qb = 0.f;
#pragma unroll
            for (int qi = 0; qi < 4; qi++) {
                ull y0 = fma2(H0, wa[2 * qi],     fma2(H1, wbp[2 * qi],     b2p[2 * qi]));
                ull y1 = fma2(H0, wa[2 * qi + 1], fma2(H1, wbp[2 * qi + 1], b2p[2 * qi + 1]));
                float ya, yb, yc, yd;
                unpack2(y0, ya, yb); unpack2(y1, yc, yd);
                const float t0 = ex2f(fminf(ya, 30.f)) + 1.f;
                const float t1 = ex2f(fminf(yb, 30.f)) + 1.f;
                const float t2 = ex2f(fminf(yc, 30.f)) + 1.f;
                const float t3 = ex2f(fminf(yd, 30.f)) + 1.f;
                const float4 x4 = *(const float4*)&sxd2[xi][4 * qi];
                const float P0 = t0 * t1;
                const float N0 = fmaf(x4.y, t0, x4.x * t1);
                const float P1 = t2 * t3;
                const float N1 = fmaf(x4.w, t2, x4.z * t3);
                const float R  = rcpf(P0 * P1);
                const float N  = fmaf(N1, P0, N0 * P1);
                if (qi & 1) qb = fmaf(R, N, qb); else qa = fmaf(R, N, qa);
            }
            const float q = qa + qb;            // k_h = Sst + q_h

            float r0 = q * w1a, r1 = q * w1b;
            redsum2(r0, r1);
            if (lane == 0) { sred[ph][warp * 2] = r0; sred[ph][warp * 2 + 1] = r1; }
            __syncthreads();
            const float4 fa = *(const float4*)&sred[ph][0];
            const float4 fb = *(const float4*)&sred[ph][4];
            const float Q0 = fa.x + fa.z + fb.x + fb.z;
            const float Q1 = fa.y + fa.w + fb.y + fb.w;
            uk0 = fmaf(Sst, SW1a, Q0);
            uk1 = fmaf(Sst, SW1b, Q1);
            s0 = fmaf(wgt, uk0, s0);
            s1 = fmaf(wgt, uk1, s1);
            ksum = fmaf(wgt, Sst + q, ksum);
            ph ^= 1;
        }

        z   = fmaf(ksum, 1.f / 6.f, z);
        uz0 = fmaf(s0,   1.f / 6.f, uz0);
        uz1 = fmaf(s1,   1.f / 6.f, uz1);

        zrow[(size_t)(t + 1) * Hh] = z;        // stream z out; projection later
    }
}

// out[b,t,:] = z[b,t,:] @ W_out + b_out.  One warp per (b,t) row.
__global__ __launch_bounds__(256) void proj_kernel(
    const float* __restrict__ W_out,    // (128, 4)
    const float* __restrict__ b_out,    // (4)
    float* __restrict__ out)            // (B*256, 4)
{
    const int row  = (blockIdx.x * 256 + threadIdx.x) >> 5;   // b*256 + t
    const int lane = threadIdx.x & 31;

    const float4 z4 = *(const float4*)&zscr[(size_t)row * Hh + lane * 4];
    const float4 w0 = *(const float4*)&W_out[(lane * 4 + 0) * 4];
    const float4 w1 = *(const float4*)&W_out[(lane * 4 + 1) * 4];
    const float4 w2 = *(const float4*)&W_out[(lane * 4 + 2) * 4];
    const float4 w3 = *(const float4*)&W_out[(lane * 4 + 3) * 4];

    float p0 = fmaf(z4.x, w0.x, fmaf(z4.y, w1.x, fmaf(z4.z, w2.x, z4.w * w3.x)));
    float p1 = fmaf(z4.x, w0.y, fmaf(z4.y, w1.y, fmaf(z4.z, w2.y, z4.w * w3.y)));
    float p2 = fmaf(z4.x, w0.z, fmaf(z4.y, w1.z, fmaf(z4.z, w2.z, z4.w * w3.z)));
    float p3 = fmaf(z4.x, w0.w, fmaf(z4.y, w1.w, fmaf(z4.z, w2.w, z4.w * w3.w)));
    redsum4(p0, p1, p2, p3);

    if (lane < 4) {
        const float v = (lane == 0) ? p0 : (lane == 1) ? p1 : (lane == 2) ? p2 : p3;
        out[(size_t)row * 4 + lane] = v + b_out[lane];
    }
}

extern "C" void kernel_launch(void* const* d_in, const int* in_sizes, int n_in,
                              void* d_out, int out_size) {
    const float* coeffs = (const float*)d_in[0];
    const float* W_init = (const float*)d_in[1];
    const float* b_init = (const float*)d_in[2];
    const float* W1     = (const float*)d_in[3];
    const float* b1     = (const float*)d_in[4];
    const float* W2     = (const float*)d_in[5];
    const float* b2     = (const float*)d_in[6];
    const float* W_out  = (const float*)d_in[7];
    const float* b_out  = (const float*)d_in[8];
    float* out = (float*)d_out;

    ncde_kernel<<<4096, 128>>>(coeffs, W_init, b_init, W1, b1, W2, b2);
    // 4096*256 rows, 8 rows per 256-thread block
    proj_kernel<<<(4096 * 256) / 8, 256>>>(W_out, b_out, out);
}